// round 10
// baseline (speedup 1.0000x reference)
#include <cuda_runtime.h>
#include <stdint.h>

#define N_NODES 100000
#define N_EDGES 1200000
#define HID     64
#define TGT     32
#define NLAY    3
#define NGRAPH  500
#define OUTW    (NLAY*TGT)   // 96
#define SCAN_B  1024
#define NBLK    ((N_NODES + SCAN_B - 1)/SCAN_B)   // 98

typedef unsigned long long ull;

// ---------------------------------------------------------------- scratch
static __device__ float g_feat[N_NODES*HID];
static __device__ float g_A   [N_NODES*HID];
static __device__ float g_h   [N_NODES*HID];
static __device__ float g_gsum [NGRAPH*HID];
static __device__ float g_gvar [NGRAPH*HID];
static __device__ float g_alpha[NGRAPH*HID];
static __device__ float g_beta [NGRAPH*HID];
static __device__ float g_ypool[NGRAPH*HID];
static __device__ float g_cnt  [NGRAPH];
static __device__ int   g_deg  [N_NODES];
static __device__ int   g_off  [N_NODES+1];
static __device__ int   g_cursor[N_NODES];
static __device__ int   g_csr  [N_EDGES];
static __device__ int   g_bsum [NBLK];

// ---------------------------------------------------------------- f32x2
__device__ __forceinline__ ull dup2(float x) {
    ull r; asm("mov.b64 %0, {%1, %1};" : "=l"(r) : "f"(x)); return r;
}
__device__ __forceinline__ ull pk2(float x, float y) {
    ull r; asm("mov.b64 %0, {%1, %2};" : "=l"(r) : "f"(x), "f"(y)); return r;
}
__device__ __forceinline__ float2 up2(ull v) {
    float lo, hi; asm("mov.b64 {%0, %1}, %2;" : "=f"(lo), "=f"(hi) : "l"(v));
    return make_float2(lo, hi);
}
__device__ __forceinline__ ull ffma2(ull a, ull b, ull c) {
    ull d; asm("fma.rn.f32x2 %0, %1, %2, %3;" : "=l"(d) : "l"(a), "l"(b), "l"(c));
    return d;
}

// ---------------------------------------------------------------- setup

__global__ void k_zero_once() {
    int i = blockIdx.x*blockDim.x + threadIdx.x;
    if (i < N_NODES) g_deg[i] = 0;
    if (i < NGRAPH)  g_cnt[i] = 0.f;
    if (i < NGRAPH*HID) { g_gsum[i] = 0.f; g_gvar[i] = 0.f; }
}

__global__ void k_hist(const int* __restrict__ dst) {
    int e = blockIdx.x*blockDim.x + threadIdx.x;
    if (e < N_EDGES) atomicAdd(&g_deg[dst[e]], 1);
}

__global__ void k_count(const int* __restrict__ gid) {
    int i = blockIdx.x*blockDim.x + threadIdx.x;
    if (i < N_NODES) atomicAdd(&g_cnt[gid[i]], 1.0f);
}

// ---------------- two-level exclusive scan of degrees

__global__ __launch_bounds__(SCAN_B) void k_scan1() {
    __shared__ int wsum[32];
    int i = blockIdx.x*SCAN_B + threadIdx.x;
    int lane = threadIdx.x & 31, wid = threadIdx.x >> 5;
    int v = (i < N_NODES) ? g_deg[i] : 0;
    int s = v;
    #pragma unroll
    for (int o = 1; o < 32; o <<= 1) {
        int t = __shfl_up_sync(~0u, s, o);
        if (lane >= o) s += t;
    }
    if (lane == 31) wsum[wid] = s;
    __syncthreads();
    if (wid == 0) {
        int ws = wsum[lane];
        #pragma unroll
        for (int o = 1; o < 32; o <<= 1) {
            int t = __shfl_up_sync(~0u, ws, o);
            if (lane >= o) ws += t;
        }
        wsum[lane] = ws;
    }
    __syncthreads();
    int excl = s - v + ((wid > 0) ? wsum[wid-1] : 0);
    if (i < N_NODES) g_off[i] = excl;
    if (threadIdx.x == SCAN_B-1) g_bsum[blockIdx.x] = wsum[31];
}

__global__ __launch_bounds__(128) void k_scan2() {
    __shared__ int buf[128];
    int tid = threadIdx.x;
    int v = (tid < NBLK) ? g_bsum[tid] : 0;
    buf[tid] = v;
    __syncthreads();
    #pragma unroll
    for (int o = 1; o < 128; o <<= 1) {
        int t = (tid >= o) ? buf[tid - o] : 0;
        __syncthreads();
        buf[tid] += t;
        __syncthreads();
    }
    if (tid < NBLK) g_bsum[tid] = buf[tid] - v;
    if (tid == 127) g_off[N_NODES] = buf[127];
}

__global__ void k_scan3() {
    int i = blockIdx.x*blockDim.x + threadIdx.x;
    if (i < N_NODES) {
        int o = g_off[i] + g_bsum[i >> 10];
        g_off[i] = o;
        g_cursor[i] = o;
    }
}

__global__ void k_scatter(const int* __restrict__ src, const int* __restrict__ dst) {
    int e = blockIdx.x*blockDim.x + threadIdx.x;
    if (e < N_EDGES) {
        int p = atomicAdd(&g_cursor[dst[e]], 1);
        g_csr[p] = src[e];
    }
}

// ------------------------------------------------ aggregation (CSR gather)
// 16 lanes per node, each lane owns 4 columns. A = (1+eps)*feat + sum(neigh)
__global__ __launch_bounds__(256) void k_agg(const float* __restrict__ x, int use_x,
                                             const float* __restrict__ eps, int l) {
    unsigned t = blockIdx.x*blockDim.x + threadIdx.x;
    unsigned node = t >> 4;
    if (node >= N_NODES) return;
    int j = (int)(t & 15u) << 2;
    const float* __restrict__ f = use_x ? x : g_feat;
    float sc = 1.0f + eps[l];
    float4 acc = *(const float4*)&f[(size_t)node*HID + j];
    acc.x *= sc; acc.y *= sc; acc.z *= sc; acc.w *= sc;
    int b = g_off[node], e = g_off[node+1];
    for (; b + 4 <= e; b += 4) {
        int s0 = g_csr[b], s1 = g_csr[b+1], s2 = g_csr[b+2], s3 = g_csr[b+3];
        float4 v0 = *(const float4*)&f[(size_t)s0*HID + j];
        float4 v1 = *(const float4*)&f[(size_t)s1*HID + j];
        float4 v2 = *(const float4*)&f[(size_t)s2*HID + j];
        float4 v3 = *(const float4*)&f[(size_t)s3*HID + j];
        acc.x += (v0.x + v1.x) + (v2.x + v3.x);
        acc.y += (v0.y + v1.y) + (v2.y + v3.y);
        acc.z += (v0.z + v1.z) + (v2.z + v3.z);
        acc.w += (v0.w + v1.w) + (v2.w + v3.w);
    }
    for (; b < e; b++) {
        int s = g_csr[b];
        float4 v = *(const float4*)&f[(size_t)s*HID + j];
        acc.x += v.x; acc.y += v.y; acc.z += v.z; acc.w += v.w;
    }
    *(float4*)&g_A[(size_t)node*HID + j] = acc;
}

// ============================================================ fused kernel 1
// MLP (2 GEMMs, col-pair x 8-row FFMA2 tile) + GraphNorm stats epilogue.
// Single weight buffer: W1 resident for GEMM1; W2 streamed in during the
// relu-write phase (same sync pair covers the WAR hazard). smem 50KB -> 34KB.
__global__ __launch_bounds__(256) void k_conv(
    const float* __restrict__ w1, const float* __restrict__ b1,
    const float* __restrict__ w2, const float* __restrict__ b2,
    const int*   __restrict__ gid)
{
    __shared__ float Ws[4096];
    __shared__ float As[64*68];
    __shared__ float b1s[64], b2s[64];
    __shared__ int   gids[64];

    const int tid  = threadIdx.x;
    const int row0 = blockIdx.x * 64;

    for (int i = tid; i < 4096; i += 256) Ws[i] = w1[i];
    if (tid < 64) {
        b1s[tid] = b1[tid]; b2s[tid] = b2[tid];
        int r = row0 + tid;
        gids[tid] = (r < N_NODES) ? gid[r] : 0;
    }
    #pragma unroll
    for (int it = 0; it < 4; it++) {
        int i = it*256 + tid;
        int r = i >> 4, kk = (i & 15) << 2;
        int row = row0 + r;
        float4 v = make_float4(0.f,0.f,0.f,0.f);
        if (row < N_NODES) v = *(const float4*)&g_A[(size_t)row*64 + kk];
        *(float4*)&As[r*68 + kk] = v;
    }
    __syncthreads();

    const int cp = tid & 31;   // column pair (2cp, 2cp+1)
    const int wr = tid >> 5;   // rows wr*8 .. wr*8+7
    const float* arow = &As[wr*8*68];

    ull acc[8];
    {
        ull bb = pk2(b1s[2*cp], b1s[2*cp+1]);
        #pragma unroll
        for (int r = 0; r < 8; r++) acc[r] = bb;
    }
    #pragma unroll 4
    for (int k = 0; k < 64; k += 4) {
        ull w0 = *(const ull*)&Ws[(k+0)*64 + 2*cp];
        ull w1v = *(const ull*)&Ws[(k+1)*64 + 2*cp];
        ull w2v = *(const ull*)&Ws[(k+2)*64 + 2*cp];
        ull w3v = *(const ull*)&Ws[(k+3)*64 + 2*cp];
        #pragma unroll
        for (int rr = 0; rr < 8; rr++) {
            float4 a = *(const float4*)&arow[rr*68 + k];
            acc[rr] = ffma2(dup2(a.x), w0,  acc[rr]);
            acc[rr] = ffma2(dup2(a.y), w1v, acc[rr]);
            acc[rr] = ffma2(dup2(a.z), w2v, acc[rr]);
            acc[rr] = ffma2(dup2(a.w), w3v, acc[rr]);
        }
    }
    __syncthreads();
    // write relu(h1) into As AND stream W2 into Ws (both guarded by next sync)
    #pragma unroll
    for (int rr = 0; rr < 8; rr++) {
        float2 h = up2(acc[rr]);
        *(float2*)&As[(wr*8+rr)*68 + 2*cp] =
            make_float2(fmaxf(h.x, 0.f), fmaxf(h.y, 0.f));
    }
    for (int i = tid; i < 4096; i += 256) Ws[i] = w2[i];
    __syncthreads();

    {
        ull bb = pk2(b2s[2*cp], b2s[2*cp+1]);
        #pragma unroll
        for (int r = 0; r < 8; r++) acc[r] = bb;
    }
    #pragma unroll 4
    for (int k = 0; k < 64; k += 4) {
        ull w0 = *(const ull*)&Ws[(k+0)*64 + 2*cp];
        ull w1v = *(const ull*)&Ws[(k+1)*64 + 2*cp];
        ull w2v = *(const ull*)&Ws[(k+2)*64 + 2*cp];
        ull w3v = *(const ull*)&Ws[(k+3)*64 + 2*cp];
        #pragma unroll
        for (int rr = 0; rr < 8; rr++) {
            float4 a = *(const float4*)&arow[rr*68 + k];
            acc[rr] = ffma2(dup2(a.x), w0,  acc[rr]);
            acc[rr] = ffma2(dup2(a.y), w1v, acc[rr]);
            acc[rr] = ffma2(dup2(a.z), w2v, acc[rr]);
            acc[rr] = ffma2(dup2(a.w), w3v, acc[rr]);
        }
    }

    // epilogue: write h, accumulate per-graph sum(h) and sum(h^2)
    float s0=0.f, s1=0.f, q0=0.f, q1=0.f;
    int cur = gids[wr*8];
    #pragma unroll
    for (int rr = 0; rr < 8; rr++) {
        int row = row0 + wr*8 + rr;
        if (row < N_NODES) {
            float2 h = up2(acc[rr]);
            *(float2*)&g_h[(size_t)row*64 + 2*cp] = h;
            int g = gids[wr*8 + rr];
            if (g != cur) {
                atomicAdd(&g_gsum[cur*64 + 2*cp],   s0);
                atomicAdd(&g_gsum[cur*64 + 2*cp+1], s1);
                atomicAdd(&g_gvar[cur*64 + 2*cp],   q0);
                atomicAdd(&g_gvar[cur*64 + 2*cp+1], q1);
                s0=s1=q0=q1=0.f; cur = g;
            }
            s0 += h.x; s1 += h.y; q0 += h.x*h.x; q1 += h.y*h.y;
        }
    }
    atomicAdd(&g_gsum[cur*64 + 2*cp],   s0);
    atomicAdd(&g_gsum[cur*64 + 2*cp+1], s1);
    atomicAdd(&g_gvar[cur*64 + 2*cp],   q0);
    atomicAdd(&g_gvar[cur*64 + 2*cp+1], q1);
}

// ------------------------------------------------ per-(graph,ch) norm coeffs
__global__ void k_stats(const float* __restrict__ gns,
                        const float* __restrict__ gnw,
                        const float* __restrict__ gnb) {
    int i = blockIdx.x*blockDim.x + threadIdx.x;
    if (i >= NGRAPH*HID) return;
    int c = i & 63, g = i >> 6;
    float n  = fmaxf(g_cnt[g], 1.f);
    float m  = g_gsum[i] / n;
    float e2 = g_gvar[i] / n;
    float s  = gns[c];
    float var = e2 - m*m*s*(2.f - s);
    float sd  = sqrtf(fmaxf(var, 0.f) + 1e-8f);
    float al  = gnw[c] / sd;
    g_alpha[i] = al;
    g_beta[i]  = gnb[c] - al*m*s;
    g_gsum[i] = 0.f;
    g_gvar[i] = 0.f;
    g_ypool[i] = 0.f;   // clean for this layer's y-pooling
}

// ============================================================ fused kernel 2
// GraphNorm affine+relu -> proj GEMM1 -> relu -> per-graph y pooling
__global__ __launch_bounds__(256) void k_proj(
    const float* __restrict__ pw1, const float* __restrict__ pb1,
    const int*   __restrict__ gid, int last)
{
    __shared__ float W1s[4096];
    __shared__ float As[64*68];
    __shared__ float b1s[64];
    __shared__ int   gids[64];

    const int tid  = threadIdx.x;
    const int row0 = blockIdx.x * 64;

    for (int i = tid; i < 4096; i += 256) W1s[i] = pw1[i];
    if (tid < 64) {
        b1s[tid] = pb1[tid];
        int r = row0 + tid;
        gids[tid] = (r < N_NODES) ? gid[r] : 0;
    }
    __syncthreads();

    // GraphNorm affine + relu -> As (+ g_feat for next layer unless last)
    #pragma unroll
    for (int it = 0; it < 4; it++) {
        int i = it*256 + tid;
        int r = i >> 4, kk = (i & 15) << 2;
        int row = row0 + r;
        float4 v = make_float4(0.f,0.f,0.f,0.f);
        if (row < N_NODES) {
            int g = gids[r];
            float4 h  = *(const float4*)&g_h[(size_t)row*64 + kk];
            float4 al = *(const float4*)&g_alpha[g*64 + kk];
            float4 be = *(const float4*)&g_beta[g*64 + kk];
            v.x = fmaxf(fmaf(al.x, h.x, be.x), 0.f);
            v.y = fmaxf(fmaf(al.y, h.y, be.y), 0.f);
            v.z = fmaxf(fmaf(al.z, h.z, be.z), 0.f);
            v.w = fmaxf(fmaf(al.w, h.w, be.w), 0.f);
            if (!last) *(float4*)&g_feat[(size_t)row*64 + kk] = v;
        }
        *(float4*)&As[r*68 + kk] = v;
    }
    __syncthreads();

    // GEMM1: 64x64, col-pair (2cp, 2cp+1) x 8 rows per thread
    const int cp = tid & 31;
    const int wr = tid >> 5;
    const float* arow = &As[wr*8*68];
    ull acc[8];
    {
        ull bb = pk2(b1s[2*cp], b1s[2*cp+1]);
        #pragma unroll
        for (int r = 0; r < 8; r++) acc[r] = bb;
    }
    #pragma unroll 4
    for (int k = 0; k < 64; k += 4) {
        ull w0 = *(const ull*)&W1s[(k+0)*64 + 2*cp];
        ull w1v = *(const ull*)&W1s[(k+1)*64 + 2*cp];
        ull w2v = *(const ull*)&W1s[(k+2)*64 + 2*cp];
        ull w3v = *(const ull*)&W1s[(k+3)*64 + 2*cp];
        #pragma unroll
        for (int rr = 0; rr < 8; rr++) {
            float4 a = *(const float4*)&arow[rr*68 + k];
            acc[rr] = ffma2(dup2(a.x), w0,  acc[rr]);
            acc[rr] = ffma2(dup2(a.y), w1v, acc[rr]);
            acc[rr] = ffma2(dup2(a.z), w2v, acc[rr]);
            acc[rr] = ffma2(dup2(a.w), w3v, acc[rr]);
        }
    }

    // pooling epilogue: y = relu(acc) summed per graph -> g_ypool
    float s0 = 0.f, s1 = 0.f;
    int cur = gids[wr*8];
    #pragma unroll
    for (int rr = 0; rr < 8; rr++) {
        int row = row0 + wr*8 + rr;
        if (row < N_NODES) {
            float2 p = up2(acc[rr]);
            float y0 = fmaxf(p.x, 0.f), y1 = fmaxf(p.y, 0.f);
            int g = gids[wr*8 + rr];
            if (g != cur) {
                atomicAdd(&g_ypool[cur*64 + 2*cp],   s0);
                atomicAdd(&g_ypool[cur*64 + 2*cp+1], s1);
                s0 = 0.f; s1 = 0.f; cur = g;
            }
            s0 += y0; s1 += y1;
        }
    }
    atomicAdd(&g_ypool[cur*64 + 2*cp],   s0);
    atomicAdd(&g_ypool[cur*64 + 2*cp+1], s1);
}

// out[g, l*32+c] = (ypool[g] @ pw2)[c] / max(n,1) + pb2[c] * min(n,1)
__global__ void k_out(const float* __restrict__ pw2, const float* __restrict__ pb2,
                      float* __restrict__ out, int l) {
    int i = blockIdx.x*blockDim.x + threadIdx.x;
    if (i >= NGRAPH*TGT) return;
    int g = i >> 5, c = i & 31;
    float acc = 0.f;
    #pragma unroll 8
    for (int k = 0; k < 64; k++)
        acc = fmaf(g_ypool[g*64 + k], pw2[k*32 + c], acc);
    float n = g_cnt[g];
    out[g*OUTW + l*TGT + c] = acc / fmaxf(n, 1.f) + pb2[c] * fminf(n, 1.f);
}

// ---------------------------------------------------------------- launcher

extern "C" void kernel_launch(void* const* d_in, const int* in_sizes, int n_in,
                              void* d_out, int out_size) {
    const float* x   = (const float*)d_in[0];
    const int*   src = (const int*)  d_in[1];
    const int*   dst = (const int*)  d_in[2];
    const int*   gid = (const int*)  d_in[3];
    const float* eps = (const float*)d_in[4];
    const float* cw1 = (const float*)d_in[5];
    const float* cb1 = (const float*)d_in[6];
    const float* cw2 = (const float*)d_in[7];
    const float* cb2 = (const float*)d_in[8];
    const float* gnw = (const float*)d_in[9];
    const float* gnb = (const float*)d_in[10];
    const float* gns = (const float*)d_in[11];
    const float* pw1 = (const float*)d_in[12];
    const float* pb1 = (const float*)d_in[13];
    const float* pw2 = (const float*)d_in[14];
    const float* pb2 = (const float*)d_in[15];
    float* out = (float*)d_out;

    const int EB = (N_EDGES + 255)/256;
    const int NB = (N_NODES + 255)/256;

    k_zero_once<<<NB, 256>>>();
    k_hist<<<EB, 256>>>(dst);
    k_count<<<NB, 256>>>(gid);
    k_scan1<<<NBLK, SCAN_B>>>();
    k_scan2<<<1, 128>>>();
    k_scan3<<<NB, 256>>>();
    k_scatter<<<EB, 256>>>(src, dst);

    const int GB = (N_NODES + 63)/64;
    const int AB = (N_NODES*16 + 255)/256;

    for (int l = 0; l < NLAY; l++) {
        int use_x = (l == 0) ? 1 : 0;
        int last  = (l == NLAY-1) ? 1 : 0;
        k_agg<<<AB, 256>>>(x, use_x, eps, l);
        k_conv<<<GB, 256>>>(cw1 + l*4096, cb1 + l*64,
                            cw2 + l*4096, cb2 + l*64, gid);
        k_stats<<<(NGRAPH*HID + 255)/256, 256>>>(gns + l*64, gnw + l*64, gnb + l*64);
        k_proj<<<GB, 256>>>(pw1 + l*4096, pb1 + l*64, gid, last);
        k_out<<<(NGRAPH*TGT + 255)/256, 256>>>(pw2 + l*2048, pb2 + l*32, out, l);
    }
}